// round 4
// baseline (speedup 1.0000x reference)
#include <cuda_runtime.h>
#include <cstdint>
#include <math.h>

#define N_NODES 10000
#define N_EDGES 160000
#define F_DIM 4
#define T_DIM 12
#define C_DIM 512
#define HID_DIM 256
#define OUT_DIM 12
#define FT (F_DIM * T_DIM)

// ---------------- scratch (__device__ globals; no allocations allowed) ----------------
__device__ float g_deg[N_NODES];
__device__ float g_dinv[N_NODES];
__device__ float g_agg[(size_t)N_NODES * FT];
__device__ float g_U[3 * F_DIM * C_DIM];          // per-gate [4][512]
__device__ float g_beff[3 * C_DIM];
__device__ float g_Uzr[F_DIM * 2 * C_DIM];        // [4][1024] z|r concat
__device__ float g_beffzr[2 * C_DIM];
__device__ float g_probs[T_DIM];
__device__ float g_H[2][(size_t)N_NODES * C_DIM];
__device__ float g_z[(size_t)N_NODES * C_DIM];
__device__ float g_Hr[(size_t)N_NODES * C_DIM];
__device__ float g_Hacc[(size_t)N_NODES * C_DIM];
__device__ float g_h1[(size_t)N_NODES * HID_DIM];
// transposed + tf32-split weights, [n][k] row-major, k stride 512:
//  [0 .. 1024*512)         : z|r concat
//  [1024*512 .. +512*512)  : h gate
//  [.. +256*512)           : W1 transposed
#define BT_ZR_OFF 0
#define BT_H_OFF  (1024 * 512)
#define BT_1_OFF  (1024 * 512 + 512 * 512)
#define BT_TOTAL  ((1024 + 512 + 256) * 512)
__device__ uint32_t g_Bthi[BT_TOTAL];
__device__ uint32_t g_Btlo[BT_TOTAL];

// ---------------- tf32 helpers ----------------
__device__ __forceinline__ void split_tf32(float x, uint32_t& hi, uint32_t& lo) {
    asm("cvt.rna.tf32.f32 %0, %1;" : "=r"(hi) : "f"(x));
    float hif = __uint_as_float(hi);
    float lof = x - hif;
    asm("cvt.rna.tf32.f32 %0, %1;" : "=r"(lo) : "f"(lof));
}
__device__ __forceinline__ void mma_tf32(float* c, const uint32_t* a, const uint32_t* b) {
    asm volatile(
        "mma.sync.aligned.m16n8k8.row.col.f32.tf32.tf32.f32 "
        "{%0,%1,%2,%3}, {%4,%5,%6,%7}, {%8,%9}, {%0,%1,%2,%3};"
        : "+f"(c[0]), "+f"(c[1]), "+f"(c[2]), "+f"(c[3])
        : "r"(a[0]), "r"(a[1]), "r"(a[2]), "r"(a[3]), "r"(b[0]), "r"(b[1]));
}

// ---------------- small setup kernels ----------------
__global__ void init_state(float* H0, float* Hacc, float* deg) {
    int idx = blockIdx.x * blockDim.x + threadIdx.x;
    if (idx < N_NODES * C_DIM) { H0[idx] = 0.f; Hacc[idx] = 0.f; }
    if (idx < N_NODES) deg[idx] = 1.f;
}
__global__ void deg_scatter(const int* __restrict__ ei, const float* __restrict__ ea,
                            float* __restrict__ deg) {
    int e = blockIdx.x * blockDim.x + threadIdx.x;
    if (e >= N_EDGES) return;
    atomicAdd(&deg[ei[N_EDGES + e]], ea[e]);
}
__global__ void compute_dinv(const float* __restrict__ deg, float* __restrict__ dinv) {
    int i = blockIdx.x * blockDim.x + threadIdx.x;
    if (i >= N_NODES) return;
    dinv[i] = rsqrtf(fmaxf(deg[i], 1e-12f));
}
__global__ void agg_init(const float* __restrict__ x, const float* __restrict__ dinv,
                         float* __restrict__ agg) {
    int idx = blockIdx.x * blockDim.x + threadIdx.x;
    if (idx >= N_NODES * FT) return;
    int i = idx / FT;
    float d = dinv[i];
    agg[idx] = d * d * x[idx];
}
__global__ void agg_scatter(const float* __restrict__ x, const int* __restrict__ ei,
                            const float* __restrict__ ea, const float* __restrict__ dinv,
                            float* __restrict__ agg) {
    long long idx = (long long)blockIdx.x * blockDim.x + threadIdx.x;
    if (idx >= (long long)N_EDGES * FT) return;
    int e = (int)(idx / FT);
    int k = (int)(idx % FT);
    int s = ei[e];
    int d = ei[N_EDGES + e];
    float coef = dinv[s] * ea[e] * dinv[d];
    atomicAdd(&agg[(size_t)d * FT + k], coef * x[(size_t)s * FT + k]);
}
__global__ void softmax12(const float* __restrict__ att, float* __restrict__ probs) {
    if (threadIdx.x == 0) {
        float m = -1e30f;
        for (int i = 0; i < T_DIM; i++) m = fmaxf(m, att[i]);
        float e[T_DIM]; float s = 0.f;
        for (int i = 0; i < T_DIM; i++) { e[i] = expf(att[i] - m); s += e[i]; }
        float inv = 1.f / s;
        for (int i = 0; i < T_DIM; i++) probs[i] = e[i] * inv;
    }
}
__global__ void compute_U(const float* Wzg, const float* Wrg, const float* Whg,
                          const float* Wzl, const float* Wrl, const float* Whl,
                          float* U) {
    int idx = blockIdx.x * blockDim.x + threadIdx.x;
    if (idx >= 3 * F_DIM * C_DIM) return;
    int g = idx / (F_DIM * C_DIM);
    int rem = idx % (F_DIM * C_DIM);
    int f = rem / C_DIM;
    int c = rem % C_DIM;
    const float* Wg = (g == 0) ? Wzg : (g == 1) ? Wrg : Whg;
    const float* Wl = (g == 0) ? Wzl : (g == 1) ? Wrl : Whl;
    float s = 0.f;
    for (int k = 0; k < C_DIM; k++) s += Wg[f * C_DIM + k] * Wl[(size_t)k * C_DIM + c];
    U[idx] = s;
}
__global__ void compute_beff(const float* bzg, const float* brg, const float* bhg,
                             const float* Wzl, const float* Wrl, const float* Whl,
                             const float* bzl, const float* brl, const float* bhl,
                             float* beff) {
    int idx = blockIdx.x * blockDim.x + threadIdx.x;
    if (idx >= 3 * C_DIM) return;
    int g = idx / C_DIM;
    int c = idx % C_DIM;
    const float* bg = (g == 0) ? bzg : (g == 1) ? brg : bhg;
    const float* Wl = (g == 0) ? Wzl : (g == 1) ? Wrl : Whl;
    const float* bl = (g == 0) ? bzl : (g == 1) ? brl : bhl;
    float s = bl[c];
    for (int k = 0; k < C_DIM; k++) s += bg[k] * Wl[(size_t)k * C_DIM + c];
    beff[idx] = s;
}
__global__ void pack_zr(const float* __restrict__ U, const float* __restrict__ beff,
                        float* __restrict__ Uzr, float* __restrict__ beffzr) {
    int idx = blockIdx.x * blockDim.x + threadIdx.x;
    if (idx < F_DIM * 1024) {
        int f = idx >> 10;
        int c = idx & 1023;
        int gt = (c >> 9);
        Uzr[idx] = U[gt * (F_DIM * C_DIM) + f * C_DIM + (c & 511)];
    }
    if (idx < 1024) {
        int gt = idx >> 9;
        beffzr[idx] = beff[gt * C_DIM + (idx & 511)];
    }
}
// build transposed + tf32-split weight planes: Bthi/Btlo[n][k]
__global__ void transpose_split_B(const float* Wzl, const float* Wrl, const float* Whl,
                                  const float* W1,
                                  uint32_t* __restrict__ Bthi, uint32_t* __restrict__ Btlo) {
    int idx = blockIdx.x * blockDim.x + threadIdx.x;
    const int ZR = 1024 * 512, HH = 512 * 512;
    if (idx >= BT_TOTAL) return;
    float v;
    if (idx < ZR) {
        int n = idx >> 9, k = idx & 511;
        v = (n < 512) ? Wzl[(size_t)(C_DIM + k) * C_DIM + n]
                      : Wrl[(size_t)(C_DIM + k) * C_DIM + (n - 512)];
    } else if (idx < ZR + HH) {
        int r = idx - ZR;
        int n = r >> 9, k = r & 511;
        v = Whl[(size_t)(C_DIM + k) * C_DIM + n];
    } else {
        int r = idx - ZR - HH;
        int n = r >> 9, k = r & 511;
        v = W1[(size_t)k * HID_DIM + n];
    }
    uint32_t hi, lo;
    split_tf32(v, hi, lo);
    Bthi[idx] = hi;
    Btlo[idx] = lo;
}

// ---------------- 3xTF32 mma.sync GEMM, presplit operands in smem, fused GRU epilogue ----------------
// C[M, Nc] = A[M,512] @ Bt^T   (Bt planes stored [Nc][512])
// mode 0 (zr): c<512 -> zb=sigmoid(v);  c>=512 -> Hr = Hin*sigmoid(v)
// mode 2 (h):  ht=tanh(v); Hn=z*Hin+(1-z)*ht -> out0=Hn; Hacc += p*Hn
// mode 3 (head): out0 = relu(v)  (A relu'd at load, no rank-4 term)
#define BMT 128
#define BNT 128
#define BKT 16
#define SPAD 20

__global__ __launch_bounds__(256) void gemm_tf32(
    const float* __restrict__ A,
    const uint32_t* __restrict__ Bthi, const uint32_t* __restrict__ Btlo,
    int M, int Nc, int mode, int t, int reluA,
    const float* __restrict__ agg, const float* __restrict__ U, int ustride,
    const float* __restrict__ beff,
    const float* __restrict__ Hin, const float* __restrict__ Z,
    float* __restrict__ out0, float* __restrict__ out1,
    float* __restrict__ Hacc, const float* __restrict__ probs)
{
    __shared__ uint32_t Ahi[BMT][SPAD];
    __shared__ uint32_t Alo[BMT][SPAD];
    __shared__ uint32_t Bhi[BNT][SPAD];
    __shared__ uint32_t Blo[BNT][SPAD];
    __shared__ float aggS[BMT][F_DIM];

    const int tid = threadIdx.x;
    const int wid = tid >> 5;
    const int lane = tid & 31;
    const int g8 = lane >> 2;       // 0..7
    const int tig = lane & 3;       // 0..3
    const int wm = wid >> 2;        // 0..1 -> m offset *64
    const int wn = wid & 3;         // 0..3 -> n offset *32
    const int row0 = blockIdx.y * BMT;
    const int col0 = blockIdx.x * BNT;

    if (mode != 3) {
        for (int i = tid; i < BMT * F_DIM; i += 256) {
            int r = i >> 2, f = i & 3;
            aggS[r][f] = (row0 + r < M) ? agg[(size_t)(row0 + r) * FT + f * T_DIM + t] : 0.f;
        }
    }

    // A-fill indices: 512 float4s per tile, 2 per thread
    const int arow0 = tid >> 2;            // 0..63
    const int ac4   = tid & 3;             // 0..3
    // B-fill indices: 512 uint4s per plane, 2 per thread
    const int brow0 = tid >> 2;
    const int bc4   = tid & 3;

    float4 pa[2];
    uint4  pbh[2], pbl[2];

    // prefetch kc=0
    {
        const int k0 = 0;
#pragma unroll
        for (int it = 0; it < 2; it++) {
            int r = arow0 + it * 64;
            pa[it] = make_float4(0.f, 0.f, 0.f, 0.f);
            if (row0 + r < M)
                pa[it] = *(const float4*)(A + (size_t)(row0 + r) * 512 + k0 + ac4 * 4);
            int n = brow0 + it * 64;
            size_t go = ((size_t)(col0 + n) * 512 + k0 + bc4 * 4) >> 2;
            pbh[it] = ((const uint4*)Bthi)[go];
            pbl[it] = ((const uint4*)Btlo)[go];
        }
    }

    float acc[4][4][4];
#pragma unroll
    for (int a = 0; a < 4; a++)
#pragma unroll
        for (int b = 0; b < 4; b++)
#pragma unroll
            for (int c = 0; c < 4; c++) acc[a][b][c] = 0.f;

    for (int kc = 0; kc < 32; kc++) {
        // ---- store prefetched tile to smem (split A on the way) ----
#pragma unroll
        for (int it = 0; it < 2; it++) {
            int r = arow0 + it * 64;
            float4 v = pa[it];
            if (reluA) {
                v.x = fmaxf(v.x, 0.f); v.y = fmaxf(v.y, 0.f);
                v.z = fmaxf(v.z, 0.f); v.w = fmaxf(v.w, 0.f);
            }
            uint32_t h0, l0, h1, l1, h2, l2, h3, l3;
            split_tf32(v.x, h0, l0); split_tf32(v.y, h1, l1);
            split_tf32(v.z, h2, l2); split_tf32(v.w, h3, l3);
            uint32_t* ah = &Ahi[r][ac4 * 4];
            uint32_t* al = &Alo[r][ac4 * 4];
            ah[0] = h0; ah[1] = h1; ah[2] = h2; ah[3] = h3;
            al[0] = l0; al[1] = l1; al[2] = l2; al[3] = l3;
            int n = brow0 + it * 64;
            *(uint4*)&Bhi[n][bc4 * 4] = pbh[it];
            *(uint4*)&Blo[n][bc4 * 4] = pbl[it];
        }
        __syncthreads();

        // ---- prefetch next tile ----
        if (kc + 1 < 32) {
            const int k0 = (kc + 1) * BKT;
#pragma unroll
            for (int it = 0; it < 2; it++) {
                int r = arow0 + it * 64;
                pa[it] = make_float4(0.f, 0.f, 0.f, 0.f);
                if (row0 + r < M)
                    pa[it] = *(const float4*)(A + (size_t)(row0 + r) * 512 + k0 + ac4 * 4);
                int n = brow0 + it * 64;
                size_t go = ((size_t)(col0 + n) * 512 + k0 + bc4 * 4) >> 2;
                pbh[it] = ((const uint4*)Bthi)[go];
                pbl[it] = ((const uint4*)Btlo)[go];
            }
        }

        // ---- compute: pure LDS + HMMA ----
#pragma unroll
        for (int kk = 0; kk < BKT; kk += 8) {
            uint32_t bh[4][2], bl[4][2];
#pragma unroll
            for (int nt = 0; nt < 4; nt++) {
                int n = wn * 32 + nt * 8 + g8;
                bh[nt][0] = Bhi[n][kk + tig];
                bh[nt][1] = Bhi[n][kk + tig + 4];
                bl[nt][0] = Blo[n][kk + tig];
                bl[nt][1] = Blo[n][kk + tig + 4];
            }
#pragma unroll
            for (int mt = 0; mt < 4; mt++) {
                int r = wm * 64 + mt * 16 + g8;
                uint32_t ah[4], al[4];
                ah[0] = Ahi[r][kk + tig];     ah[1] = Ahi[r + 8][kk + tig];
                ah[2] = Ahi[r][kk + tig + 4]; ah[3] = Ahi[r + 8][kk + tig + 4];
                al[0] = Alo[r][kk + tig];     al[1] = Alo[r + 8][kk + tig];
                al[2] = Alo[r][kk + tig + 4]; al[3] = Alo[r + 8][kk + tig + 4];
#pragma unroll
                for (int nt = 0; nt < 4; nt++) {
                    mma_tf32(acc[mt][nt], ah, bh[nt]);
                    mma_tf32(acc[mt][nt], ah, bl[nt]);
                    mma_tf32(acc[mt][nt], al, bh[nt]);
                }
            }
        }
        __syncthreads();
    }

    // ---- fused epilogue ----
    const float p = (mode == 2) ? probs[t] : 0.f;
#pragma unroll
    for (int mt = 0; mt < 4; mt++) {
#pragma unroll
        for (int i = 0; i < 2; i++) {
            int rl = wm * 64 + mt * 16 + g8 + i * 8;
            int gr = row0 + rl;
            if (gr >= M) continue;
            float a0 = 0.f, a1 = 0.f, a2 = 0.f, a3 = 0.f;
            if (mode != 3) {
                a0 = aggS[rl][0]; a1 = aggS[rl][1];
                a2 = aggS[rl][2]; a3 = aggS[rl][3];
            }
#pragma unroll
            for (int nt = 0; nt < 4; nt++) {
#pragma unroll
                for (int jj = 0; jj < 2; jj++) {
                    int cg = col0 + wn * 32 + nt * 8 + tig * 2 + jj;
                    float v = acc[mt][nt][i * 2 + jj] + beff[cg];
                    if (mode != 3)
                        v += a0 * U[cg] + a1 * U[ustride + cg]
                           + a2 * U[2 * ustride + cg] + a3 * U[3 * ustride + cg];
                    if (mode == 0) {
                        float s = 1.f / (1.f + expf(-v));
                        if (cg < 512) {
                            out0[(size_t)gr * C_DIM + cg] = s;
                        } else {
                            size_t o = (size_t)gr * C_DIM + (cg - 512);
                            out1[o] = Hin[o] * s;
                        }
                    } else if (mode == 2) {
                        size_t o = (size_t)gr * C_DIM + cg;
                        float ht = tanhf(v);
                        float zz = Z[o];
                        float hn = zz * Hin[o] + (1.f - zz) * ht;
                        out0[o] = hn;
                        Hacc[o] += p * hn;
                    } else {
                        out0[(size_t)gr * HID_DIM + cg] = fmaxf(v, 0.f);
                    }
                }
            }
        }
    }
}

// out[i,j] = h1[i,:] @ W2[:,j] + b2[j]
__global__ void head2(const float* __restrict__ h1, const float* __restrict__ W2,
                      const float* __restrict__ b2, float* __restrict__ out) {
    int idx = blockIdx.x * blockDim.x + threadIdx.x;
    if (idx >= N_NODES * OUT_DIM) return;
    int i = idx / OUT_DIM;
    int j = idx % OUT_DIM;
    float s = b2[j];
    const float* hr = h1 + (size_t)i * HID_DIM;
    for (int k = 0; k < HID_DIM; k++) s += hr[k] * W2[k * OUT_DIM + j];
    out[idx] = s;
}
__global__ void copy_hidden(const float* __restrict__ Hacc, float* __restrict__ out) {
    int idx = blockIdx.x * blockDim.x + threadIdx.x;
    if (idx >= N_NODES * C_DIM) return;
    out[idx] = Hacc[idx];
}

// ---------------- host launcher ----------------
extern "C" void kernel_launch(void* const* d_in, const int* in_sizes, int n_in,
                              void* d_out, int out_size) {
    const float* x   = (const float*)d_in[0];
    const int*   ei  = (const int*)d_in[1];
    const float* ea  = (const float*)d_in[2];
    const float* att = (const float*)d_in[3];
    const float* Wg[3] = {(const float*)d_in[4],  (const float*)d_in[8],  (const float*)d_in[12]};
    const float* bg[3] = {(const float*)d_in[5],  (const float*)d_in[9],  (const float*)d_in[13]};
    const float* Wl[3] = {(const float*)d_in[6],  (const float*)d_in[10], (const float*)d_in[14]};
    const float* bl[3] = {(const float*)d_in[7],  (const float*)d_in[11], (const float*)d_in[15]};
    const float* W1 = (const float*)d_in[16];
    const float* b1 = (const float*)d_in[17];
    const float* W2 = (const float*)d_in[18];
    const float* b2 = (const float*)d_in[19];
    float* out = (float*)d_out;

    float *deg, *dinv, *agg, *U, *beff, *Uzr, *beffzr, *probs, *Hbase, *zb, *Hr, *Hacc, *h1;
    uint32_t *Bthi, *Btlo;
    cudaGetSymbolAddress((void**)&deg,    g_deg);
    cudaGetSymbolAddress((void**)&dinv,   g_dinv);
    cudaGetSymbolAddress((void**)&agg,    g_agg);
    cudaGetSymbolAddress((void**)&U,      g_U);
    cudaGetSymbolAddress((void**)&beff,   g_beff);
    cudaGetSymbolAddress((void**)&Uzr,    g_Uzr);
    cudaGetSymbolAddress((void**)&beffzr, g_beffzr);
    cudaGetSymbolAddress((void**)&probs,  g_probs);
    cudaGetSymbolAddress((void**)&Hbase,  g_H);
    cudaGetSymbolAddress((void**)&zb,     g_z);
    cudaGetSymbolAddress((void**)&Hr,     g_Hr);
    cudaGetSymbolAddress((void**)&Hacc,   g_Hacc);
    cudaGetSymbolAddress((void**)&h1,     g_h1);
    cudaGetSymbolAddress((void**)&Bthi,   g_Bthi);
    cudaGetSymbolAddress((void**)&Btlo,   g_Btlo);
    float* H[2] = {Hbase, Hbase + (size_t)N_NODES * C_DIM};

    // setup
    init_state<<<(N_NODES * C_DIM + 255) / 256, 256>>>(H[0], Hacc, deg);
    deg_scatter<<<(N_EDGES + 255) / 256, 256>>>(ei, ea, deg);
    compute_dinv<<<(N_NODES + 255) / 256, 256>>>(deg, dinv);
    agg_init<<<(N_NODES * FT + 255) / 256, 256>>>(x, dinv, agg);
    {
        long long tot = (long long)N_EDGES * FT;
        agg_scatter<<<(unsigned)((tot + 255) / 256), 256>>>(x, ei, ea, dinv, agg);
    }
    softmax12<<<1, 32>>>(att, probs);
    compute_U<<<(3 * F_DIM * C_DIM + 255) / 256, 256>>>(Wg[0], Wg[1], Wg[2], Wl[0], Wl[1], Wl[2], U);
    compute_beff<<<(3 * C_DIM + 255) / 256, 256>>>(bg[0], bg[1], bg[2], Wl[0], Wl[1], Wl[2],
                                                   bl[0], bl[1], bl[2], beff);
    pack_zr<<<(F_DIM * 1024 + 255) / 256, 256>>>(U, beff, Uzr, beffzr);
    transpose_split_B<<<(BT_TOTAL + 255) / 256, 256>>>(Wl[0], Wl[1], Wl[2], W1, Bthi, Btlo);

    dim3 blk(256);
    dim3 gridZR(1024 / BNT, (N_NODES + BMT - 1) / BMT);   // (8, 79)
    dim3 gridH(512 / BNT, (N_NODES + BMT - 1) / BMT);     // (4, 79)
    int hin = 0;
    for (int t = 0; t < T_DIM; t++) {
        // fused z+r gates: z -> zb, Hr = H*r
        gemm_tf32<<<gridZR, blk>>>(H[hin], Bthi + BT_ZR_OFF, Btlo + BT_ZR_OFF,
                                   N_NODES, 1024, 0, t, 0,
                                   agg, Uzr, 1024, beffzr,
                                   H[hin], nullptr, zb, Hr, nullptr, probs);
        // h gate: Hnew = z*H + (1-z)*tanh(...); Hacc += p*Hnew
        gemm_tf32<<<gridH, blk>>>(Hr, Bthi + BT_H_OFF, Btlo + BT_H_OFF,
                                  N_NODES, 512, 2, t, 0,
                                  agg, U + 2 * F_DIM * C_DIM, 512, beff + 2 * C_DIM,
                                  H[hin], zb, H[1 - hin], nullptr, Hacc, probs);
        hin ^= 1;
    }

    // head: h1 = relu(relu(Hacc) @ W1 + b1)
    dim3 gridHead(HID_DIM / BNT, (N_NODES + BMT - 1) / BMT);   // (2, 79)
    gemm_tf32<<<gridHead, blk>>>(Hacc, Bthi + BT_1_OFF, Btlo + BT_1_OFF,
                                 N_NODES, HID_DIM, 3, 0, 1,
                                 nullptr, nullptr, 0, b1,
                                 nullptr, nullptr, h1, nullptr, nullptr, probs);
    head2<<<(N_NODES * OUT_DIM + 255) / 256, 256>>>(h1, W2, b2, out);
    copy_hidden<<<(N_NODES * C_DIM + 255) / 256, 256>>>(Hacc, out + (size_t)N_NODES * OUT_DIM);
}

// round 5
// speedup vs baseline: 1.8189x; 1.8189x over previous
#include <cuda_runtime.h>
#include <cuda_bf16.h>
#include <cstdint>
#include <math.h>

#define N_NODES 10000
#define N_EDGES 160000
#define F_DIM 4
#define T_DIM 12
#define C_DIM 512
#define HID_DIM 256
#define OUT_DIM 12
#define FT (F_DIM * T_DIM)

// ---------------- scratch (__device__ globals; no allocations allowed) ----------------
__device__ float g_deg[N_NODES];
__device__ float g_dinv[N_NODES];
__device__ float g_agg[(size_t)N_NODES * FT];
__device__ float g_U[3 * F_DIM * C_DIM];          // per-gate [4][512]
__device__ float g_beff[3 * C_DIM];
__device__ float g_Uzr[F_DIM * 2 * C_DIM];        // [4][1024] z|r concat
__device__ float g_beffzr[2 * C_DIM];
__device__ float g_probs[T_DIM];
__device__ float g_H[2][(size_t)N_NODES * C_DIM];
__device__ float g_z[(size_t)N_NODES * C_DIM];
__device__ float g_Hr[(size_t)N_NODES * C_DIM];
__device__ float g_Hacc[(size_t)N_NODES * C_DIM];
__device__ float g_h1[(size_t)N_NODES * HID_DIM];
// transposed + bf16-split weights, [n][k] with k packed in bf16x2 (uint32 holds k=2j,2j+1)
//  pair-offsets (uint32 units):
#define BT_ZR_OFF 0
#define BT_H_OFF  (1024 * 256)
#define BT_1_OFF  (1024 * 256 + 512 * 256)
#define BT_PAIRS  ((1024 + 512 + 256) * 256)
__device__ uint32_t g_Bthi[BT_PAIRS];
__device__ uint32_t g_Btlo[BT_PAIRS];

// ---------------- bf16 helpers ----------------
// pack two floats (lo = a, hi = b) as bf16x2
__device__ __forceinline__ uint32_t pack_bf16x2(float a, float b) {
    uint32_t r;
    asm("cvt.rn.bf16x2.f32 %0, %1, %2;" : "=r"(r) : "f"(b), "f"(a));
    return r;
}
__device__ __forceinline__ void mma_bf16(float* c, const uint32_t* a, const uint32_t* b) {
    asm volatile(
        "mma.sync.aligned.m16n8k16.row.col.f32.bf16.bf16.f32 "
        "{%0,%1,%2,%3}, {%4,%5,%6,%7}, {%8,%9}, {%0,%1,%2,%3};"
        : "+f"(c[0]), "+f"(c[1]), "+f"(c[2]), "+f"(c[3])
        : "r"(a[0]), "r"(a[1]), "r"(a[2]), "r"(a[3]), "r"(b[0]), "r"(b[1]));
}

// ---------------- small setup kernels ----------------
__global__ void init_state(float* H0, float* Hacc, float* deg) {
    int idx = blockIdx.x * blockDim.x + threadIdx.x;
    if (idx < N_NODES * C_DIM) { H0[idx] = 0.f; Hacc[idx] = 0.f; }
    if (idx < N_NODES) deg[idx] = 1.f;
}
__global__ void deg_scatter(const int* __restrict__ ei, const float* __restrict__ ea,
                            float* __restrict__ deg) {
    int e = blockIdx.x * blockDim.x + threadIdx.x;
    if (e >= N_EDGES) return;
    atomicAdd(&deg[ei[N_EDGES + e]], ea[e]);
}
__global__ void compute_dinv(const float* __restrict__ deg, float* __restrict__ dinv) {
    int i = blockIdx.x * blockDim.x + threadIdx.x;
    if (i >= N_NODES) return;
    dinv[i] = rsqrtf(fmaxf(deg[i], 1e-12f));
}
__global__ void agg_init(const float* __restrict__ x, const float* __restrict__ dinv,
                         float* __restrict__ agg) {
    int idx = blockIdx.x * blockDim.x + threadIdx.x;
    if (idx >= N_NODES * FT) return;
    int i = idx / FT;
    float d = dinv[i];
    agg[idx] = d * d * x[idx];
}
__global__ void agg_scatter(const float* __restrict__ x, const int* __restrict__ ei,
                            const float* __restrict__ ea, const float* __restrict__ dinv,
                            float* __restrict__ agg) {
    long long idx = (long long)blockIdx.x * blockDim.x + threadIdx.x;
    if (idx >= (long long)N_EDGES * FT) return;
    int e = (int)(idx / FT);
    int k = (int)(idx % FT);
    int s = ei[e];
    int d = ei[N_EDGES + e];
    float coef = dinv[s] * ea[e] * dinv[d];
    atomicAdd(&agg[(size_t)d * FT + k], coef * x[(size_t)s * FT + k]);
}
__global__ void softmax12(const float* __restrict__ att, float* __restrict__ probs) {
    if (threadIdx.x == 0) {
        float m = -1e30f;
        for (int i = 0; i < T_DIM; i++) m = fmaxf(m, att[i]);
        float e[T_DIM]; float s = 0.f;
        for (int i = 0; i < T_DIM; i++) { e[i] = expf(att[i] - m); s += e[i]; }
        float inv = 1.f / s;
        for (int i = 0; i < T_DIM; i++) probs[i] = e[i] * inv;
    }
}
__global__ void compute_U(const float* Wzg, const float* Wrg, const float* Whg,
                          const float* Wzl, const float* Wrl, const float* Whl,
                          float* U) {
    int idx = blockIdx.x * blockDim.x + threadIdx.x;
    if (idx >= 3 * F_DIM * C_DIM) return;
    int g = idx / (F_DIM * C_DIM);
    int rem = idx % (F_DIM * C_DIM);
    int f = rem / C_DIM;
    int c = rem % C_DIM;
    const float* Wg = (g == 0) ? Wzg : (g == 1) ? Wrg : Whg;
    const float* Wl = (g == 0) ? Wzl : (g == 1) ? Wrl : Whl;
    float s = 0.f;
    for (int k = 0; k < C_DIM; k++) s += Wg[f * C_DIM + k] * Wl[(size_t)k * C_DIM + c];
    U[idx] = s;
}
__global__ void compute_beff(const float* bzg, const float* brg, const float* bhg,
                             const float* Wzl, const float* Wrl, const float* Whl,
                             const float* bzl, const float* brl, const float* bhl,
                             float* beff) {
    int idx = blockIdx.x * blockDim.x + threadIdx.x;
    if (idx >= 3 * C_DIM) return;
    int g = idx / C_DIM;
    int c = idx % C_DIM;
    const float* bg = (g == 0) ? bzg : (g == 1) ? brg : bhg;
    const float* Wl = (g == 0) ? Wzl : (g == 1) ? Wrl : Whl;
    const float* bl = (g == 0) ? bzl : (g == 1) ? brl : bhl;
    float s = bl[c];
    for (int k = 0; k < C_DIM; k++) s += bg[k] * Wl[(size_t)k * C_DIM + c];
    beff[idx] = s;
}
__global__ void pack_zr(const float* __restrict__ U, const float* __restrict__ beff,
                        float* __restrict__ Uzr, float* __restrict__ beffzr) {
    int idx = blockIdx.x * blockDim.x + threadIdx.x;
    if (idx < F_DIM * 1024) {
        int f = idx >> 10;
        int c = idx & 1023;
        int gt = (c >> 9);
        Uzr[idx] = U[gt * (F_DIM * C_DIM) + f * C_DIM + (c & 511)];
    }
    if (idx < 1024) {
        int gt = idx >> 9;
        beffzr[idx] = beff[gt * C_DIM + (idx & 511)];
    }
}
// transposed + bf16-split + pair-packed weight planes
__global__ void transpose_split_B(const float* Wzl, const float* Wrl, const float* Whl,
                                  const float* W1,
                                  uint32_t* __restrict__ Bthi, uint32_t* __restrict__ Btlo) {
    int idx = blockIdx.x * blockDim.x + threadIdx.x;   // pair index
    if (idx >= BT_PAIRS) return;
    const int ZR = 1024 * 256, HH = 512 * 256;
    float v0, v1;
    if (idx < ZR) {
        int n = idx >> 8, pk = idx & 255;
        int k0 = pk * 2;
        if (n < 512) {
            v0 = Wzl[(size_t)(C_DIM + k0) * C_DIM + n];
            v1 = Wzl[(size_t)(C_DIM + k0 + 1) * C_DIM + n];
        } else {
            v0 = Wrl[(size_t)(C_DIM + k0) * C_DIM + (n - 512)];
            v1 = Wrl[(size_t)(C_DIM + k0 + 1) * C_DIM + (n - 512)];
        }
    } else if (idx < ZR + HH) {
        int r = idx - ZR;
        int n = r >> 8, pk = r & 255;
        int k0 = pk * 2;
        v0 = Whl[(size_t)(C_DIM + k0) * C_DIM + n];
        v1 = Whl[(size_t)(C_DIM + k0 + 1) * C_DIM + n];
    } else {
        int r = idx - ZR - HH;
        int n = r >> 8, pk = r & 255;
        int k0 = pk * 2;
        v0 = W1[(size_t)k0 * HID_DIM + n];
        v1 = W1[(size_t)(k0 + 1) * HID_DIM + n];
    }
    float h0 = __bfloat162float(__float2bfloat16_rn(v0));
    float h1 = __bfloat162float(__float2bfloat16_rn(v1));
    Bthi[idx] = pack_bf16x2(v0, v1);
    Btlo[idx] = pack_bf16x2(v0 - h0, v1 - h1);
}

// ---------------- 3x bf16 mma.sync GEMM (m16n8k16), fused GRU epilogue ----------------
// C[M, Nc] = A[M,512] @ Bt^T   (Bt planes stored [Nc][512] bf16-pair-packed)
// mode 0 (zr): c<512 -> zb=sigmoid(v);  c>=512 -> Hr = Hin*sigmoid(v)
// mode 2 (h):  ht=tanh(v); Hn=z*Hin+(1-z)*ht -> out0=Hn; Hacc += p*Hn
// mode 3 (head): out0 = relu(v)  (A relu'd at load, no rank-4 term)
#define BMT 128
#define BNT 128
#define BKT 32              // k elements per chunk (16 uint32 pairs)
#define SPAD 20             // uint32 per row (16 + 4 pad)

__global__ __launch_bounds__(256, 2) void gemm_bf16(
    const float* __restrict__ A,
    const uint32_t* __restrict__ Bthi, const uint32_t* __restrict__ Btlo,
    int M, int Nc, int mode, int t, int reluA,
    const float* __restrict__ agg, const float* __restrict__ U, int ustride,
    const float* __restrict__ beff,
    const float* __restrict__ Hin, const float* __restrict__ Z,
    float* __restrict__ out0, float* __restrict__ out1,
    float* __restrict__ Hacc, const float* __restrict__ probs)
{
    __shared__ uint32_t Ahi[BMT][SPAD];
    __shared__ uint32_t Alo[BMT][SPAD];
    __shared__ uint32_t Bhi[BNT][SPAD];
    __shared__ uint32_t Blo[BNT][SPAD];
    __shared__ float aggS[BMT][F_DIM];

    const int tid = threadIdx.x;
    const int wid = tid >> 5;
    const int lane = tid & 31;
    const int g8 = lane >> 2;       // 0..7
    const int tig = lane & 3;       // 0..3
    const int wm = wid >> 2;        // 0..1 -> m offset *64
    const int wn = wid & 3;         // 0..3 -> n offset *32
    const int row0 = blockIdx.y * BMT;
    const int col0 = blockIdx.x * BNT;

    if (mode != 3) {
        for (int i = tid; i < BMT * F_DIM; i += 256) {
            int r = i >> 2, f = i & 3;
            aggS[r][f] = (row0 + r < M) ? agg[(size_t)(row0 + r) * FT + f * T_DIM + t] : 0.f;
        }
    }

    float acc[4][4][4];
#pragma unroll
    for (int a = 0; a < 4; a++)
#pragma unroll
        for (int b = 0; b < 4; b++)
#pragma unroll
            for (int c = 0; c < 4; c++) acc[a][b][c] = 0.f;

    for (int kc = 0; kc < 16; kc++) {
        const int k0 = kc * BKT;
        // ---- A tile [128 x 32] fp32 -> split bf16 pairs in smem ----
#pragma unroll
        for (int it = 0; it < 4; it++) {
            int idx = it * 256 + tid;      // 0..1023
            int r = idx >> 3;              // 0..127
            int c4 = idx & 7;              // float4 index within 32 floats
            float4 v = make_float4(0.f, 0.f, 0.f, 0.f);
            if (row0 + r < M)
                v = *(const float4*)(A + (size_t)(row0 + r) * 512 + k0 + c4 * 4);
            if (reluA) {
                v.x = fmaxf(v.x, 0.f); v.y = fmaxf(v.y, 0.f);
                v.z = fmaxf(v.z, 0.f); v.w = fmaxf(v.w, 0.f);
            }
            float hx = __bfloat162float(__float2bfloat16_rn(v.x));
            float hy = __bfloat162float(__float2bfloat16_rn(v.y));
            float hz = __bfloat162float(__float2bfloat16_rn(v.z));
            float hw = __bfloat162float(__float2bfloat16_rn(v.w));
            Ahi[r][c4 * 2 + 0] = pack_bf16x2(v.x, v.y);
            Ahi[r][c4 * 2 + 1] = pack_bf16x2(v.z, v.w);
            Alo[r][c4 * 2 + 0] = pack_bf16x2(v.x - hx, v.y - hy);
            Alo[r][c4 * 2 + 1] = pack_bf16x2(v.z - hz, v.w - hw);
        }
        // ---- B tile [128 x 32] packed pairs ----
#pragma unroll
        for (int it = 0; it < 2; it++) {
            int idx = it * 256 + tid;      // 0..511
            int n = idx >> 2;              // 0..127
            int q = idx & 3;               // uint4 index (4 per row-chunk)
            size_t go = (size_t)(col0 + n) * 64 + kc * 4 + q;   // uint4 units (256 u32/row)
            uint4 vh = ((const uint4*)Bthi)[go];
            uint4 vl = ((const uint4*)Btlo)[go];
            *(uint4*)&Bhi[n][q * 4] = vh;
            *(uint4*)&Blo[n][q * 4] = vl;
        }
        __syncthreads();

        // ---- compute: per kb (k=16), distance-4 accumulator chains ----
#pragma unroll
        for (int kb = 0; kb < 16; kb += 8) {
            uint32_t bh[4][2], bl[4][2];
#pragma unroll
            for (int nt = 0; nt < 4; nt++) {
                int n = wn * 32 + nt * 8 + g8;
                bh[nt][0] = Bhi[n][kb + tig];
                bh[nt][1] = Bhi[n][kb + tig + 4];
                bl[nt][0] = Blo[n][kb + tig];
                bl[nt][1] = Blo[n][kb + tig + 4];
            }
#pragma unroll
            for (int mt = 0; mt < 4; mt++) {
                int r = wm * 64 + mt * 16 + g8;
                uint32_t ah[4], al[4];
                ah[0] = Ahi[r][kb + tig];     ah[1] = Ahi[r + 8][kb + tig];
                ah[2] = Ahi[r][kb + tig + 4]; ah[3] = Ahi[r + 8][kb + tig + 4];
                al[0] = Alo[r][kb + tig];     al[1] = Alo[r + 8][kb + tig];
                al[2] = Alo[r][kb + tig + 4]; al[3] = Alo[r + 8][kb + tig + 4];
#pragma unroll
                for (int nt = 0; nt < 4; nt++) mma_bf16(acc[mt][nt], ah, bh[nt]);
#pragma unroll
                for (int nt = 0; nt < 4; nt++) mma_bf16(acc[mt][nt], ah, bl[nt]);
#pragma unroll
                for (int nt = 0; nt < 4; nt++) mma_bf16(acc[mt][nt], al, bh[nt]);
            }
        }
        __syncthreads();
    }

    // ---- fused epilogue ----
    const float p = (mode == 2) ? probs[t] : 0.f;
#pragma unroll
    for (int mt = 0; mt < 4; mt++) {
#pragma unroll
        for (int i = 0; i < 2; i++) {
            int rl = wm * 64 + mt * 16 + g8 + i * 8;
            int gr = row0 + rl;
            if (gr >= M) continue;
            float a0 = 0.f, a1 = 0.f, a2 = 0.f, a3 = 0.f;
            if (mode != 3) {
                a0 = aggS[rl][0]; a1 = aggS[rl][1];
                a2 = aggS[rl][2]; a3 = aggS[rl][3];
            }
#pragma unroll
            for (int nt = 0; nt < 4; nt++) {
#pragma unroll
                for (int jj = 0; jj < 2; jj++) {
                    int cg = col0 + wn * 32 + nt * 8 + tig * 2 + jj;
                    float v = acc[mt][nt][i * 2 + jj] + beff[cg];
                    if (mode != 3)
                        v += a0 * U[cg] + a1 * U[ustride + cg]
                           + a2 * U[2 * ustride + cg] + a3 * U[3 * ustride + cg];
                    if (mode == 0) {
                        float s = 1.f / (1.f + expf(-v));
                        if (cg < 512) {
                            out0[(size_t)gr * C_DIM + cg] = s;
                        } else {
                            size_t o = (size_t)gr * C_DIM + (cg - 512);
                            out1[o] = Hin[o] * s;
                        }
                    } else if (mode == 2) {
                        size_t o = (size_t)gr * C_DIM + cg;
                        float ht = tanhf(v);
                        float zz = Z[o];
                        float hn = zz * Hin[o] + (1.f - zz) * ht;
                        out0[o] = hn;
                        Hacc[o] += p * hn;
                    } else {
                        out0[(size_t)gr * HID_DIM + cg] = fmaxf(v, 0.f);
                    }
                }
            }
        }
    }
}

// out[i,j] = h1[i,:] @ W2[:,j] + b2[j]
__global__ void head2(const float* __restrict__ h1, const float* __restrict__ W2,
                      const float* __restrict__ b2, float* __restrict__ out) {
    int idx = blockIdx.x * blockDim.x + threadIdx.x;
    if (idx >= N_NODES * OUT_DIM) return;
    int i = idx / OUT_DIM;
    int j = idx % OUT_DIM;
    float s = b2[j];
    const float* hr = h1 + (size_t)i * HID_DIM;
    for (int k = 0; k < HID_DIM; k++) s += hr[k] * W2[k * OUT_DIM + j];
    out[idx] = s;
}
__global__ void copy_hidden(const float* __restrict__ Hacc, float* __restrict__ out) {
    int idx = blockIdx.x * blockDim.x + threadIdx.x;
    if (idx >= N_NODES * C_DIM) return;
    out[idx] = Hacc[idx];
}

// ---------------- host launcher ----------------
extern "C" void kernel_launch(void* const* d_in, const int* in_sizes, int n_in,
                              void* d_out, int out_size) {
    const float* x   = (const float*)d_in[0];
    const int*   ei  = (const int*)d_in[1];
    const float* ea  = (const float*)d_in[2];
    const float* att = (const float*)d_in[3];
    const float* Wg[3] = {(const float*)d_in[4],  (const float*)d_in[8],  (const float*)d_in[12]};
    const float* bg[3] = {(const float*)d_in[5],  (const float*)d_in[9],  (const float*)d_in[13]};
    const float* Wl[3] = {(const float*)d_in[6],  (const float*)d_in[10], (const float*)d_in[14]};
    const float* bl[3] = {(const float*)d_in[7],  (const float*)d_in[11], (const float*)d_in[15]};
    const float* W1 = (const float*)d_in[16];
    const float* b1 = (const float*)d_in[17];
    const float* W2 = (const float*)d_in[18];
    const float* b2 = (const float*)d_in[19];
    float* out = (float*)d_out;

    float *deg, *dinv, *agg, *U, *beff, *Uzr, *beffzr, *probs, *Hbase, *zb, *Hr, *Hacc, *h1;
    uint32_t *Bthi, *Btlo;
    cudaGetSymbolAddress((void**)&deg,    g_deg);
    cudaGetSymbolAddress((void**)&dinv,   g_dinv);
    cudaGetSymbolAddress((void**)&agg,    g_agg);
    cudaGetSymbolAddress((void**)&U,      g_U);
    cudaGetSymbolAddress((void**)&beff,   g_beff);
    cudaGetSymbolAddress((void**)&Uzr,    g_Uzr);
    cudaGetSymbolAddress((void**)&beffzr, g_beffzr);
    cudaGetSymbolAddress((void**)&probs,  g_probs);
    cudaGetSymbolAddress((void**)&Hbase,  g_H);
    cudaGetSymbolAddress((void**)&zb,     g_z);
    cudaGetSymbolAddress((void**)&Hr,     g_Hr);
    cudaGetSymbolAddress((void**)&Hacc,   g_Hacc);
    cudaGetSymbolAddress((void**)&h1,     g_h1);
    cudaGetSymbolAddress((void**)&Bthi,   g_Bthi);
    cudaGetSymbolAddress((void**)&Btlo,   g_Btlo);
    float* H[2] = {Hbase, Hbase + (size_t)N_NODES * C_DIM};

    // setup
    init_state<<<(N_NODES * C_DIM + 255) / 256, 256>>>(H[0], Hacc, deg);
    deg_scatter<<<(N_EDGES + 255) / 256, 256>>>(ei, ea, deg);
    compute_dinv<<<(N_NODES + 255) / 256, 256>>>(deg, dinv);
    agg_init<<<(N_NODES * FT + 255) / 256, 256>>>(x, dinv, agg);
    {
        long long tot = (long long)N_EDGES * FT;
        agg_scatter<<<(unsigned)((tot + 255) / 256), 256>>>(x, ei, ea, dinv, agg);
    }
    softmax12<<<1, 32>>>(att, probs);
    compute_U<<<(3 * F_DIM * C_DIM + 255) / 256, 256>>>(Wg[0], Wg[1], Wg[2], Wl[0], Wl[1], Wl[2], U);
    compute_beff<<<(3 * C_DIM + 255) / 256, 256>>>(bg[0], bg[1], bg[2], Wl[0], Wl[1], Wl[2],
                                                   bl[0], bl[1], bl[2], beff);
    pack_zr<<<(F_DIM * 1024 + 255) / 256, 256>>>(U, beff, Uzr, beffzr);
    transpose_split_B<<<(BT_PAIRS + 255) / 256, 256>>>(Wl[0], Wl[1], Wl[2], W1, Bthi, Btlo);

    dim3 blk(256);
    dim3 gridZR(1024 / BNT, (N_NODES + BMT - 1) / BMT);   // (8, 79)
    dim3 gridH(512 / BNT, (N_NODES + BMT - 1) / BMT);     // (4, 79)
    int hin = 0;
    for (int t = 0; t < T_DIM; t++) {
        // fused z+r gates: z -> zb, Hr = H*r
        gemm_bf16<<<gridZR, blk>>>(H[hin], Bthi + BT_ZR_OFF, Btlo + BT_ZR_OFF,
                                   N_NODES, 1024, 0, t, 0,
                                   agg, Uzr, 1024, beffzr,
                                   H[hin], nullptr, zb, Hr, nullptr, probs);
        // h gate: Hnew = z*H + (1-z)*tanh(...); Hacc += p*Hnew
        gemm_bf16<<<gridH, blk>>>(Hr, Bthi + BT_H_OFF, Btlo + BT_H_OFF,
                                  N_NODES, 512, 2, t, 0,
                                  agg, U + 2 * F_DIM * C_DIM, 512, beff + 2 * C_DIM,
                                  H[hin], zb, H[1 - hin], nullptr, Hacc, probs);
        hin ^= 1;
    }

    // head: h1 = relu(relu(Hacc) @ W1 + b1)
    dim3 gridHead(HID_DIM / BNT, (N_NODES + BMT - 1) / BMT);   // (2, 79)
    gemm_bf16<<<gridHead, blk>>>(Hacc, Bthi + BT_1_OFF, Btlo + BT_1_OFF,
                                 N_NODES, HID_DIM, 3, 0, 1,
                                 nullptr, nullptr, 0, b1,
                                 nullptr, nullptr, h1, nullptr, nullptr, probs);
    head2<<<(N_NODES * OUT_DIM + 255) / 256, 256>>>(h1, W2, b2, out);
    copy_hidden<<<(N_NODES * C_DIM + 255) / 256, 256>>>(Hacc, out + (size_t)N_NODES * OUT_DIM);
}